// round 15
// baseline (speedup 1.0000x reference)
#include <cuda_runtime.h>
#include <cuda_bf16.h>
#include <cuda_fp16.h>
#include <cstdint>

#define N0 50000
#define N1 12500
#define N2 3125
#define E0 800000
#define E1 200000
#define E2 50000
#define ET (E0 + E1 + E2)
#define NT (N0 + N1 + N2)
#define D 128

#define T0 13
#define T1 4
#define T2 1
#define NB (T0 + T1 + T2)

#define RP0 0
#define RP1 (N0 + 1)
#define RP2 (N0 + N1 + 2)

// ---------------- scratch (device globals) ----------------
__device__ __half g_t[N0 * D];
__device__ float g_enc0[N0 * D];
__device__ float g_enc1[N1 * D];
__device__ float g_h[N0 * D];
__device__ float g_h2[N0 * D];

__device__ int      g_deg[NT];
__device__ int      g_rp[NT + 3];
__device__ int      g_cur[NT];
__device__ float    g_dis[NT];
__device__ int      g_seq[ET];
__device__ uint32_t g_es[ET];      // packed edge: [31:16] fp16(dis[src]), [15:0] src

// ---------------- helpers ----------------
__device__ __forceinline__ float4 ld_h4(const __half* __restrict__ t, size_t r, int lane) {
    uint2 raw = __ldg((const uint2*)(t + r * D) + lane);
    float2 a = __half22float2(*(__half2*)&raw.x);
    float2 b = __half22float2(*(__half2*)&raw.y);
    return make_float4(a.x, a.y, b.x, b.y);
}

__device__ __forceinline__ uint32_t smem_u32(const void* p) {
    uint32_t a;
    asm("{ .reg .u64 tmp; cvta.to.shared.u64 tmp, %1; cvt.u32.u64 %0, tmp; }"
        : "=r"(a) : "l"(p));
    return a;
}

__device__ __forceinline__ void mma_f16(float* d, const unsigned* a, unsigned b0, unsigned b1) {
    asm volatile(
        "mma.sync.aligned.m16n8k16.row.col.f32.f16.f16.f32 "
        "{%0,%1,%2,%3}, {%4,%5,%6,%7}, {%8,%9}, {%0,%1,%2,%3};"
        : "+f"(d[0]), "+f"(d[1]), "+f"(d[2]), "+f"(d[3])
        : "r"(a[0]), "r"(a[1]), "r"(a[2]), "r"(a[3]), "r"(b0), "r"(b1));
}

__device__ __forceinline__ void ldm_x4(unsigned* r, uint32_t addr) {
    asm volatile("ldmatrix.sync.aligned.m8n8.x4.shared.b16 {%0,%1,%2,%3}, [%4];"
        : "=r"(r[0]), "=r"(r[1]), "=r"(r[2]), "=r"(r[3]) : "r"(addr));
}
__device__ __forceinline__ void ldm_x4t(unsigned* r, uint32_t addr) {
    asm volatile("ldmatrix.sync.aligned.m8n8.x4.trans.shared.b16 {%0,%1,%2,%3}, [%4];"
        : "=r"(r[0]), "=r"(r[1]), "=r"(r[2]), "=r"(r[3]) : "r"(addr));
}

// unpack packed edge -> (src, dis)
__device__ __forceinline__ void unpack_e(uint32_t e, int& src, float& dv) {
    src = (int)(e & 0xFFFFu);
    __half hb = __ushort_as_half((unsigned short)(e >> 16));
    dv = __half2float(hb);
}

// ---------------- utility kernels ----------------
__global__ void zero_init_k(int* deg, float4* h, float4* h2) {
    int i = blockIdx.x * blockDim.x + threadIdx.x;
    if (i < NT) deg[i] = 0;
    int nh = N1 * D / 4;
    for (int j = i; j < nh; j += gridDim.x * blockDim.x)
        h[j] = make_float4(0.f, 0.f, 0.f, 0.f);
    int nh2 = N2 * D / 4;
    for (int j = i; j < nh2; j += gridDim.x * blockDim.x)
        h2[j] = make_float4(0.f, 0.f, 0.f, 0.f);
}

// ---------------- CSR pass 1: histogram + sequence numbers ----------------
__global__ void hist_seq_k(const int* __restrict__ e0, const int* __restrict__ e1,
                           const int* __restrict__ e2, int* __restrict__ deg,
                           int* __restrict__ seq) {
    int i = blockIdx.x * blockDim.x + threadIdx.x;
    int i4 = i * 4;
    const int* p;
    int base, soff;
    if (i4 < E0)           { p = e0 + E0 + i4;             base = 0;       soff = i4; }
    else if (i4 < E0 + E1) { int j = i4 - E0;      p = e1 + E1 + j; base = N0;      soff = E0 + j; }
    else if (i4 < ET)      { int j = i4 - E0 - E1; p = e2 + E2 + j; base = N0 + N1; soff = E0 + E1 + j; }
    else return;
    int4 c = *(const int4*)p;
    int s0 = atomicAdd(&deg[base + c.x], 1);
    int s1 = atomicAdd(&deg[base + c.y], 1);
    int s2 = atomicAdd(&deg[base + c.z], 1);
    int s3 = atomicAdd(&deg[base + c.w], 1);
    *(int4*)(seq + soff) = make_int4(s0, s1, s2, s3);
}

__device__ __forceinline__ void tile_map(int b, int& noff, int& ng, int& t, int& rpoff) {
    if (b < T0)           { noff = 0;       ng = N0; t = b;           rpoff = RP0; }
    else if (b < T0 + T1) { noff = N0;      ng = N1; t = b - T0;      rpoff = RP1; }
    else                  { noff = N0 + N1; ng = N2; t = b - T0 - T1; rpoff = RP2; }
}

// ---------------- fused scan ----------------
__global__ void scan_fused_k(const int* __restrict__ deg, int* __restrict__ rp,
                             int* __restrict__ cur, float* __restrict__ dis) {
    int noff, ng, t, rpoff;
    tile_map(blockIdx.x, noff, ng, t, rpoff);
    int tid = threadIdx.x;
    int lane = tid & 31, w = tid >> 5;
    __shared__ int ws[32];
    __shared__ int s_pre;

    {
        int lim = t * 4096;
        int s = 0;
        for (int i = tid * 4; i < lim; i += 4096) {
            int4 v = *(const int4*)(deg + noff + i);
            s += v.x + v.y + v.z + v.w;
        }
#pragma unroll
        for (int o = 16; o; o >>= 1) s += __shfl_xor_sync(0xffffffffu, s, o);
        if (lane == 0) ws[w] = s;
        __syncthreads();
        if (w == 0) {
            int v = ws[lane];
#pragma unroll
            for (int o = 16; o; o >>= 1) v += __shfl_xor_sync(0xffffffffu, v, o);
            if (lane == 0) s_pre = v;
        }
        __syncthreads();
    }

    int i = t * 4096 + tid * 4;
    int v[4];
    int s = 0;
#pragma unroll
    for (int q = 0; q < 4; q++) {
        int l = i + q;
        v[q] = (l < ng) ? deg[noff + l] : 0;
        s += v[q];
    }
    int incl = s;
#pragma unroll
    for (int o = 1; o < 32; o <<= 1) {
        int tv = __shfl_up_sync(0xffffffffu, incl, o);
        if (lane >= o) incl += tv;
    }
    __syncthreads();
    if (lane == 31) ws[w] = incl;
    __syncthreads();
    if (w == 0) {
        int x = ws[lane];
#pragma unroll
        for (int o = 1; o < 32; o <<= 1) {
            int tv = __shfl_up_sync(0xffffffffu, x, o);
            if (lane >= o) x += tv;
        }
        ws[lane] = x;
    }
    __syncthreads();
    int base = s_pre + (w > 0 ? ws[w - 1] : 0) + (incl - s);
    int run = base;
#pragma unroll
    for (int q = 0; q < 4; q++) {
        int l = i + q;
        if (l < ng) {
            rp[rpoff + l] = run;
            cur[noff + l] = run;
            dis[noff + l] = rsqrtf((float)(v[q] + 1));
            run += v[q];
        }
    }
    bool last = (t == ((ng + 4095) / 4096) - 1);
    if (last && tid == 1023) rp[rpoff + ng] = s_pre + ws[31];
}

// ---------------- CSR pass 2: atomic-free positioned scatter (packed 4B edges) ----
__global__ void scatter_pos_k(const int* __restrict__ e0, const int* __restrict__ e1,
                              const int* __restrict__ e2, const int* __restrict__ cur,
                              const float* __restrict__ dis, const int* __restrict__ seq,
                              uint32_t* __restrict__ es) {
    int i = blockIdx.x * blockDim.x + threadIdx.x;
    int i4 = i * 4;
    const int* pe;
    int nb, sb, E, j;
    if (i4 < E0)           { pe = e0; nb = 0;       sb = 0;       E = E0; j = i4; }
    else if (i4 < E0 + E1) { pe = e1; nb = N0;      sb = E0;      E = E1; j = i4 - E0; }
    else if (i4 < ET)      { pe = e2; nb = N0 + N1; sb = E0 + E1; E = E2; j = i4 - E0 - E1; }
    else return;
    int4 c = *(const int4*)(pe + E + j);
    int4 r = *(const int4*)(pe + j);
    int4 s = *(const int4*)(seq + sb + j);
    int p0 = cur[nb + c.x] + s.x;
    int p1 = cur[nb + c.y] + s.y;
    int p2 = cur[nb + c.z] + s.z;
    int p3 = cur[nb + c.w] + s.w;
    uint32_t d0 = (uint32_t)__half_as_ushort(__float2half_rn(dis[nb + r.x]));
    uint32_t d1 = (uint32_t)__half_as_ushort(__float2half_rn(dis[nb + r.y]));
    uint32_t d2 = (uint32_t)__half_as_ushort(__float2half_rn(dis[nb + r.z]));
    uint32_t d3 = (uint32_t)__half_as_ushort(__float2half_rn(dis[nb + r.w]));
    es[sb + p0] = (d0 << 16) | (uint32_t)r.x;
    es[sb + p1] = (d1 << 16) | (uint32_t)r.y;
    es[sb + p2] = (d2 << 16) | (uint32_t)r.z;
    es[sb + p3] = (d3 << 16) | (uint32_t)r.w;
}

// ---------------- fp16 tensor-core GEMM (mma.m16n8k16 + ldmatrix) ----------------
#define KS 136
#define GH_SMEM (2 * 128 * KS * 2)

template<bool GATHER>
__global__ __launch_bounds__(512, 2) void gemm_h16(
    const float* __restrict__ A, const float* __restrict__ W,
    __half* __restrict__ C, int rows,
    const float* __restrict__ hsrc, int h_rows,
    const int* __restrict__ idx, const float* __restrict__ val,
    const float* __restrict__ enc)
{
    extern __shared__ __half smh[];
    __half* Ws = smh;
    __half* As = smh + 128 * KS;
    int tid = threadIdx.x;
    int lane = tid & 31;
    int w = tid >> 5;
    int wm = w & 3, wn = w >> 2;
    int gid = lane >> 2, tig = lane & 3;
    int tile = blockIdx.x;

#pragma unroll
    for (int j = 0; j < 8; j++) {
        int fi = tid + j * 512;
        int k = fi >> 5;
        int c4 = fi & 31;
        float4 v = *(const float4*)(W + (size_t)k * D + c4 * 4);
        __half2 p0 = __floats2half2_rn(v.x, v.y);
        __half2 p1 = __floats2half2_rn(v.z, v.w);
        uint2 pk;
        pk.x = *(uint32_t*)&p0;
        pk.y = *(uint32_t*)&p1;
        *(uint2*)(Ws + k * KS + c4 * 4) = pk;
    }
#pragma unroll
    for (int j = 0; j < 8; j++) {
        int fi = tid + j * 512;
        int m = fi >> 5;
        int c4 = fi & 31;
        int gr = tile * 128 + m;
        float4 v = make_float4(0.f, 0.f, 0.f, 0.f);
        if (gr < rows) {
            if (GATHER) {
                int ci = min(idx[gr], h_rows - 1);
                float vv = val[gr];
                float4 u = *(const float4*)(hsrc + (size_t)ci * D + c4 * 4);
                float4 e = *(const float4*)(enc + (size_t)gr * D + c4 * 4);
                v = make_float4(vv * u.x + e.x, vv * u.y + e.y,
                                vv * u.z + e.z, vv * u.w + e.w);
            } else {
                v = *(const float4*)(A + (size_t)gr * D + c4 * 4);
            }
        }
        __half2 p0 = __floats2half2_rn(v.x, v.y);
        __half2 p1 = __floats2half2_rn(v.z, v.w);
        uint2 pk;
        pk.x = *(uint32_t*)&p0;
        pk.y = *(uint32_t*)&p1;
        *(uint2*)(As + m * KS + c4 * 4) = pk;
    }
    __syncthreads();

    uint32_t uWs = smem_u32(Ws);
    uint32_t uAs = smem_u32(As);
    uint32_t aAddr[2];
#pragma unroll
    for (int mt = 0; mt < 2; mt++)
        aAddr[mt] = uAs + (((wm * 32 + mt * 16 + (lane & 15)) * KS
                           + ((lane >> 4) << 3)) << 1);
    uint32_t bAddr[2];
#pragma unroll
    for (int np = 0; np < 2; np++)
        bAddr[np] = uWs + ((((lane & 15)) * KS
                           + wn * 32 + np * 16 + ((lane >> 4) << 3)) << 1);

    float acc[2][4][4];
#pragma unroll
    for (int mt = 0; mt < 2; mt++)
#pragma unroll
        for (int nt = 0; nt < 4; nt++)
#pragma unroll
            for (int q = 0; q < 4; q++) acc[mt][nt][q] = 0.f;

#pragma unroll
    for (int ks = 0; ks < 8; ks++) {
        unsigned a[2][4], b[2][4];
        ldm_x4(a[0], aAddr[0] + ks * 32);
        ldm_x4(a[1], aAddr[1] + ks * 32);
        ldm_x4t(b[0], bAddr[0] + ks * 32 * KS);
        ldm_x4t(b[1], bAddr[1] + ks * 32 * KS);
#pragma unroll
        for (int np = 0; np < 2; np++) {
            mma_f16(acc[0][2 * np],     a[0], b[np][0], b[np][1]);
            mma_f16(acc[1][2 * np],     a[1], b[np][0], b[np][1]);
            mma_f16(acc[0][2 * np + 1], a[0], b[np][2], b[np][3]);
            mma_f16(acc[1][2 * np + 1], a[1], b[np][2], b[np][3]);
        }
    }

#pragma unroll
    for (int mt = 0; mt < 2; mt++) {
        int r1 = tile * 128 + wm * 32 + mt * 16 + gid;
        int r2 = r1 + 8;
#pragma unroll
        for (int nt = 0; nt < 4; nt++) {
            int col = wn * 32 + nt * 8 + 2 * tig;
            if (r1 < rows)
                *(__half2*)(C + (size_t)r1 * D + col) =
                    __floats2half2_rn(acc[mt][nt][0], acc[mt][nt][1]);
            if (r2 < rows)
                *(__half2*)(C + (size_t)r2 * D + col) =
                    __floats2half2_rn(acc[mt][nt][2], acc[mt][nt][3]);
        }
    }
}

// ---------------- aggregation (warp/dst, unroll4, fp16 gathers, packed 4B edges) ---
template<int MODE>   // 0 = plain, 1 = fused pool scatter, 2 = fused normalize
__global__ void agg_k(const __half* __restrict__ t, int h_rows,
                      const int* __restrict__ rp, const uint32_t* __restrict__ es,
                      const float* __restrict__ dis, int n,
                      const float* __restrict__ bias, float* __restrict__ out,
                      const int* __restrict__ pidx, const float* __restrict__ pval,
                      float* __restrict__ pout) {
    int warp = (blockIdx.x * blockDim.x + threadIdx.x) >> 5;
    int lane = threadIdx.x & 31;
    if (warp >= n) return;
    int dst = warp;
    float dd = dis[dst];
    int hc = h_rows - 1;
    float4 v = ld_h4(t, (size_t)min(dst, hc), lane);
    float w0 = dd * dd;
    float4 a1 = make_float4(w0 * v.x, w0 * v.y, w0 * v.z, w0 * v.w);
    float4 a2 = make_float4(0.f, 0.f, 0.f, 0.f);
    float4 a3 = make_float4(0.f, 0.f, 0.f, 0.f);
    float4 a4 = make_float4(0.f, 0.f, 0.f, 0.f);
    int e = rp[dst], end = rp[dst + 1];
    for (; e + 4 <= end; e += 4) {
        uint32_t f0 = es[e], f1 = es[e + 1], f2 = es[e + 2], f3 = es[e + 3];
        int s0, s1, s2, s3;
        float d0, d1, d2, d3;
        unpack_e(f0, s0, d0); unpack_e(f1, s1, d1);
        unpack_e(f2, s2, d2); unpack_e(f3, s3, d3);
        float q0 = d0 * dd, q1 = d1 * dd, q2 = d2 * dd, q3 = d3 * dd;
        float4 u0 = ld_h4(t, (size_t)min(s0, hc), lane);
        float4 u1 = ld_h4(t, (size_t)min(s1, hc), lane);
        float4 u2 = ld_h4(t, (size_t)min(s2, hc), lane);
        float4 u3 = ld_h4(t, (size_t)min(s3, hc), lane);
        a1.x += q0 * u0.x; a1.y += q0 * u0.y; a1.z += q0 * u0.z; a1.w += q0 * u0.w;
        a2.x += q1 * u1.x; a2.y += q1 * u1.y; a2.z += q1 * u1.z; a2.w += q1 * u1.w;
        a3.x += q2 * u2.x; a3.y += q2 * u2.y; a3.z += q2 * u2.z; a3.w += q2 * u2.w;
        a4.x += q3 * u3.x; a4.y += q3 * u3.y; a4.z += q3 * u3.z; a4.w += q3 * u3.w;
    }
    for (; e < end; e++) {
        int s0; float d0;
        unpack_e(es[e], s0, d0);
        float q0 = d0 * dd;
        float4 u0 = ld_h4(t, (size_t)min(s0, hc), lane);
        a1.x += q0 * u0.x; a1.y += q0 * u0.y; a1.z += q0 * u0.z; a1.w += q0 * u0.w;
    }
    float4 b = ((const float4*)bias)[lane];
    float4 r;
    r.x = fmaxf(a1.x + a2.x + a3.x + a4.x + b.x, 0.f);
    r.y = fmaxf(a1.y + a2.y + a3.y + a4.y + b.y, 0.f);
    r.z = fmaxf(a1.z + a2.z + a3.z + a4.z + b.z, 0.f);
    r.w = fmaxf(a1.w + a2.w + a3.w + a4.w + b.w, 0.f);
    if (MODE == 2) {
        float s = r.x * r.x + r.y * r.y + r.z * r.z + r.w * r.w;
#pragma unroll
        for (int o = 16; o; o >>= 1) s += __shfl_xor_sync(0xffffffffu, s, o);
        float inv = 1.0f / fmaxf(sqrtf(s), 1e-12f);
        r.x *= inv; r.y *= inv; r.z *= inv; r.w *= inv;
    }
    ((float4*)(out + (size_t)dst * D))[lane] = r;
    if (MODE == 1) {
        int c = pidx[dst];
        float pv = pval[dst];
        float* o = pout + (size_t)c * D + lane * 4;
        atomicAdd(o + 0, pv * r.x);
        atomicAdd(o + 1, pv * r.y);
        atomicAdd(o + 2, pv * r.z);
        atomicAdd(o + 3, pv * r.w);
    }
}

// ---------------- host orchestration ----------------
static inline int cdiv(int a, int b) { return (a + b - 1) / b; }

extern "C" void kernel_launch(void* const* d_in, const int* in_sizes, int n_in,
                              void* d_out, int out_size) {
    const float* x   = (const float*)d_in[0];
    const int* e0    = (const int*)d_in[1];
    const int* e1    = (const int*)d_in[2];
    const int* e2    = (const int*)d_in[3];
    const int* C0i   = (const int*)d_in[4];
    const float* C0v = (const float*)d_in[5];
    const int* C1i   = (const int*)d_in[6];
    const float* C1v = (const float*)d_in[7];
    const float* W_enc0 = (const float*)d_in[8];
    const float* b_enc0 = (const float*)d_in[9];
    const float* W_enc1 = (const float*)d_in[10];
    const float* b_enc1 = (const float*)d_in[11];
    const float* W_enc2 = (const float*)d_in[12];
    const float* b_enc2 = (const float*)d_in[13];
    const float* W_bot  = (const float*)d_in[14];
    const float* b_bot  = (const float*)d_in[15];
    const float* W_dec0 = (const float*)d_in[16];
    const float* b_dec0 = (const float*)d_in[17];
    const float* W_dec1 = (const float*)d_in[18];
    const float* b_dec1 = (const float*)d_in[19];
    const float* W_dec2 = (const float*)d_in[20];
    const float* b_dec2 = (const float*)d_in[21];

    __half* t;
    float *enc0, *enc1, *h, *h2, *dis;
    int *deg, *rp, *cur, *seq;
    uint32_t* es;
    cudaGetSymbolAddress((void**)&t, g_t);
    cudaGetSymbolAddress((void**)&enc0, g_enc0);
    cudaGetSymbolAddress((void**)&enc1, g_enc1);
    cudaGetSymbolAddress((void**)&h, g_h);
    cudaGetSymbolAddress((void**)&h2, g_h2);
    cudaGetSymbolAddress((void**)&deg, g_deg);
    cudaGetSymbolAddress((void**)&rp, g_rp);
    cudaGetSymbolAddress((void**)&cur, g_cur);
    cudaGetSymbolAddress((void**)&seq, g_seq);
    cudaGetSymbolAddress((void**)&es, g_es);
    cudaGetSymbolAddress((void**)&dis, g_dis);

    cudaFuncSetAttribute((const void*)gemm_h16<false>, cudaFuncAttributeMaxDynamicSharedMemorySize, GH_SMEM);
    cudaFuncSetAttribute((const void*)gemm_h16<true>,  cudaFuncAttributeMaxDynamicSharedMemorySize, GH_SMEM);

    const int* rp0 = rp + RP0; const uint32_t* es0 = es;           const float* dis0 = dis;
    const int* rp1 = rp + RP1; const uint32_t* es1 = es + E0;      const float* dis1 = dis + N0;
    const int* rp2 = rp + RP2; const uint32_t* es2 = es + E0 + E1; const float* dis2 = dis + N0 + N1;

    const int AT = 256;

    auto gemm = [&](const float* A, const float* W, int rows) {
        gemm_h16<false><<<cdiv(rows, 128), 512, GH_SMEM>>>(A, W, t, rows, nullptr, 0, nullptr, nullptr, nullptr);
    };
    auto gemm_g = [&](const float* W, int rows, const float* hsrc, int h_rows,
                      const int* idx, const float* val, const float* enc) {
        gemm_h16<true><<<cdiv(rows, 128), 512, GH_SMEM>>>(nullptr, W, t, rows, hsrc, h_rows, idx, val, enc);
    };

    // ---- CSR build (two-pass, atomic-free scatter, packed 4B edges) + zero h/h2 ----
    zero_init_k<<<cdiv(NT, 1024), 1024>>>(deg, (float4*)h, (float4*)h2);
    hist_seq_k<<<cdiv(ET / 4, 256), 256>>>(e0, e1, e2, deg, seq);
    scan_fused_k<<<NB, 1024>>>(deg, rp, cur, dis);
    scatter_pos_k<<<cdiv(ET / 4, 256), 256>>>(e0, e1, e2, cur, dis, seq, es);

    // ---- encoder level 0: agg fuses pool0 -> h (N1 rows) ----
    gemm(x, W_enc0, N0);
    agg_k<1><<<cdiv(N0, 8), AT>>>(t, N0, rp0, es0, dis0, N0, b_enc0, enc0, C0i, C0v, h);
    // ---- encoder level 1: agg fuses pool1 -> h2 (N2 rows, pre-zeroed) ----
    gemm(h, W_enc1, N1);
    agg_k<1><<<cdiv(N1, 8), AT>>>(t, N1, rp1, es1, dis1, N1, b_enc1, enc1, C1i, C1v, h2);
    // ---- encoder level 2: h2 -> h ----
    gemm(h2, W_enc2, N2);
    agg_k<0><<<cdiv(N2, 8), AT>>>(t, N2, rp2, es2, dis2, N2, b_enc2, h, nullptr, nullptr, nullptr);
    // ---- bottleneck: h -> h2 ----
    gemm(h, W_bot, N2);
    agg_k<0><<<cdiv(N2, 8), AT>>>(t, N2, rp2, es2, dis2, N2, b_bot, h2, nullptr, nullptr, nullptr);
    // ---- decoder l=2: unpool C1 from h2 (N2 rows), conv g2 -> h ----
    gemm_g(W_dec2, N1, h2, N2, C1i, C1v, enc1);
    agg_k<0><<<cdiv(N2, 8), AT>>>(t, N1, rp2, es2, dis2, N2, b_dec2, h, nullptr, nullptr, nullptr);
    // ---- decoder l=1: unpool C0 from h (N2 rows, clamped), conv g1 -> h2 ----
    gemm_g(W_dec1, N0, h, N2, C0i, C0v, enc0);
    agg_k<0><<<cdiv(N1, 8), AT>>>(t, N0, rp1, es1, dis1, N1, b_dec1, h2, nullptr, nullptr, nullptr);
    // ---- decoder l=0 + fused normalize: h2 (N1 rows) -> out ----
    gemm(h2, W_dec0, N1);
    agg_k<2><<<cdiv(N0, 8), AT>>>(t, N1, rp0, es0, dis0, N0, b_dec0, (float*)d_out, nullptr, nullptr, nullptr);
}

// round 16
// speedup vs baseline: 1.0106x; 1.0106x over previous
#include <cuda_runtime.h>
#include <cuda_bf16.h>
#include <cuda_fp16.h>
#include <cstdint>

#define N0 50000
#define N1 12500
#define N2 3125
#define E0 800000
#define E1 200000
#define E2 50000
#define ET (E0 + E1 + E2)
#define NT (N0 + N1 + N2)
#define D 128

#define T0 13
#define T1 4
#define T2 1
#define NB (T0 + T1 + T2)

#define RP0 0
#define RP1 (N0 + 1)
#define RP2 (N0 + N1 + 2)

// ---------------- scratch (device globals) ----------------
__device__ __half g_t[N0 * D];
__device__ float g_enc0[N0 * D];
__device__ float g_enc1[N1 * D];
__device__ float g_h[N0 * D];
__device__ float g_h2[N0 * D];

__device__ int      g_deg[NT];
__device__ int      g_rp[NT + 3];
__device__ int      g_cur[NT];
__device__ float    g_dis[NT];
__device__ int      g_seq[ET];
__device__ uint32_t g_es[ET];      // packed edge: [31:16] fp16(dis[src]), [15:0] src

// ---------------- helpers ----------------
__device__ __forceinline__ float4 ld_h4(const __half* __restrict__ t, size_t r, int lane) {
    uint2 raw = __ldg((const uint2*)(t + r * D) + lane);
    float2 a = __half22float2(*(__half2*)&raw.x);
    float2 b = __half22float2(*(__half2*)&raw.y);
    return make_float4(a.x, a.y, b.x, b.y);
}

__device__ __forceinline__ uint32_t smem_u32(const void* p) {
    uint32_t a;
    asm("{ .reg .u64 tmp; cvta.to.shared.u64 tmp, %1; cvt.u32.u64 %0, tmp; }"
        : "=r"(a) : "l"(p));
    return a;
}

__device__ __forceinline__ void mma_f16(float* d, const unsigned* a, unsigned b0, unsigned b1) {
    asm volatile(
        "mma.sync.aligned.m16n8k16.row.col.f32.f16.f16.f32 "
        "{%0,%1,%2,%3}, {%4,%5,%6,%7}, {%8,%9}, {%0,%1,%2,%3};"
        : "+f"(d[0]), "+f"(d[1]), "+f"(d[2]), "+f"(d[3])
        : "r"(a[0]), "r"(a[1]), "r"(a[2]), "r"(a[3]), "r"(b0), "r"(b1));
}

__device__ __forceinline__ void ldm_x4(unsigned* r, uint32_t addr) {
    asm volatile("ldmatrix.sync.aligned.m8n8.x4.shared.b16 {%0,%1,%2,%3}, [%4];"
        : "=r"(r[0]), "=r"(r[1]), "=r"(r[2]), "=r"(r[3]) : "r"(addr));
}
__device__ __forceinline__ void ldm_x4t(unsigned* r, uint32_t addr) {
    asm volatile("ldmatrix.sync.aligned.m8n8.x4.trans.shared.b16 {%0,%1,%2,%3}, [%4];"
        : "=r"(r[0]), "=r"(r[1]), "=r"(r[2]), "=r"(r[3]) : "r"(addr));
}

// unpack packed edge -> (src, dis)
__device__ __forceinline__ void unpack_e(uint32_t e, int& src, float& dv) {
    src = (int)(e & 0xFFFFu);
    __half hb = __ushort_as_half((unsigned short)(e >> 16));
    dv = __half2float(hb);
}

// ---------------- utility kernels ----------------
__global__ void zero_init_k(int* deg, float4* h, float4* h2) {
    int i = blockIdx.x * blockDim.x + threadIdx.x;
    if (i < NT) deg[i] = 0;
    int nh = N1 * D / 4;
    for (int j = i; j < nh; j += gridDim.x * blockDim.x)
        h[j] = make_float4(0.f, 0.f, 0.f, 0.f);
    int nh2 = N2 * D / 4;
    for (int j = i; j < nh2; j += gridDim.x * blockDim.x)
        h2[j] = make_float4(0.f, 0.f, 0.f, 0.f);
}

// ---------------- CSR pass 1: histogram + sequence numbers ----------------
__global__ void hist_seq_k(const int* __restrict__ e0, const int* __restrict__ e1,
                           const int* __restrict__ e2, int* __restrict__ deg,
                           int* __restrict__ seq) {
    int i = blockIdx.x * blockDim.x + threadIdx.x;
    int i4 = i * 4;
    const int* p;
    int base, soff;
    if (i4 < E0)           { p = e0 + E0 + i4;             base = 0;       soff = i4; }
    else if (i4 < E0 + E1) { int j = i4 - E0;      p = e1 + E1 + j; base = N0;      soff = E0 + j; }
    else if (i4 < ET)      { int j = i4 - E0 - E1; p = e2 + E2 + j; base = N0 + N1; soff = E0 + E1 + j; }
    else return;
    int4 c = *(const int4*)p;
    int s0 = atomicAdd(&deg[base + c.x], 1);
    int s1 = atomicAdd(&deg[base + c.y], 1);
    int s2 = atomicAdd(&deg[base + c.z], 1);
    int s3 = atomicAdd(&deg[base + c.w], 1);
    *(int4*)(seq + soff) = make_int4(s0, s1, s2, s3);
}

__device__ __forceinline__ void tile_map(int b, int& noff, int& ng, int& t, int& rpoff) {
    if (b < T0)           { noff = 0;       ng = N0; t = b;           rpoff = RP0; }
    else if (b < T0 + T1) { noff = N0;      ng = N1; t = b - T0;      rpoff = RP1; }
    else                  { noff = N0 + N1; ng = N2; t = b - T0 - T1; rpoff = RP2; }
}

// ---------------- fused scan ----------------
__global__ void scan_fused_k(const int* __restrict__ deg, int* __restrict__ rp,
                             int* __restrict__ cur, float* __restrict__ dis) {
    int noff, ng, t, rpoff;
    tile_map(blockIdx.x, noff, ng, t, rpoff);
    int tid = threadIdx.x;
    int lane = tid & 31, w = tid >> 5;
    __shared__ int ws[32];
    __shared__ int s_pre;

    {
        int lim = t * 4096;
        int s = 0;
        for (int i = tid * 4; i < lim; i += 4096) {
            int4 v = *(const int4*)(deg + noff + i);
            s += v.x + v.y + v.z + v.w;
        }
#pragma unroll
        for (int o = 16; o; o >>= 1) s += __shfl_xor_sync(0xffffffffu, s, o);
        if (lane == 0) ws[w] = s;
        __syncthreads();
        if (w == 0) {
            int v = ws[lane];
#pragma unroll
            for (int o = 16; o; o >>= 1) v += __shfl_xor_sync(0xffffffffu, v, o);
            if (lane == 0) s_pre = v;
        }
        __syncthreads();
    }

    int i = t * 4096 + tid * 4;
    int v[4];
    int s = 0;
#pragma unroll
    for (int q = 0; q < 4; q++) {
        int l = i + q;
        v[q] = (l < ng) ? deg[noff + l] : 0;
        s += v[q];
    }
    int incl = s;
#pragma unroll
    for (int o = 1; o < 32; o <<= 1) {
        int tv = __shfl_up_sync(0xffffffffu, incl, o);
        if (lane >= o) incl += tv;
    }
    __syncthreads();
    if (lane == 31) ws[w] = incl;
    __syncthreads();
    if (w == 0) {
        int x = ws[lane];
#pragma unroll
        for (int o = 1; o < 32; o <<= 1) {
            int tv = __shfl_up_sync(0xffffffffu, x, o);
            if (lane >= o) x += tv;
        }
        ws[lane] = x;
    }
    __syncthreads();
    int base = s_pre + (w > 0 ? ws[w - 1] : 0) + (incl - s);
    int run = base;
#pragma unroll
    for (int q = 0; q < 4; q++) {
        int l = i + q;
        if (l < ng) {
            rp[rpoff + l] = run;
            cur[noff + l] = run;
            dis[noff + l] = rsqrtf((float)(v[q] + 1));
            run += v[q];
        }
    }
    bool last = (t == ((ng + 4095) / 4096) - 1);
    if (last && tid == 1023) rp[rpoff + ng] = s_pre + ws[31];
}

// ---------------- CSR pass 2: atomic-free positioned scatter (packed 4B edges) ----
__global__ void scatter_pos_k(const int* __restrict__ e0, const int* __restrict__ e1,
                              const int* __restrict__ e2, const int* __restrict__ cur,
                              const float* __restrict__ dis, const int* __restrict__ seq,
                              uint32_t* __restrict__ es) {
    int i = blockIdx.x * blockDim.x + threadIdx.x;
    int i4 = i * 4;
    const int* pe;
    int nb, sb, E, j;
    if (i4 < E0)           { pe = e0; nb = 0;       sb = 0;       E = E0; j = i4; }
    else if (i4 < E0 + E1) { pe = e1; nb = N0;      sb = E0;      E = E1; j = i4 - E0; }
    else if (i4 < ET)      { pe = e2; nb = N0 + N1; sb = E0 + E1; E = E2; j = i4 - E0 - E1; }
    else return;
    int4 c = *(const int4*)(pe + E + j);
    int4 r = *(const int4*)(pe + j);
    int4 s = *(const int4*)(seq + sb + j);
    int p0 = cur[nb + c.x] + s.x;
    int p1 = cur[nb + c.y] + s.y;
    int p2 = cur[nb + c.z] + s.z;
    int p3 = cur[nb + c.w] + s.w;
    uint32_t d0 = (uint32_t)__half_as_ushort(__float2half_rn(dis[nb + r.x]));
    uint32_t d1 = (uint32_t)__half_as_ushort(__float2half_rn(dis[nb + r.y]));
    uint32_t d2 = (uint32_t)__half_as_ushort(__float2half_rn(dis[nb + r.z]));
    uint32_t d3 = (uint32_t)__half_as_ushort(__float2half_rn(dis[nb + r.w]));
    es[sb + p0] = (d0 << 16) | (uint32_t)r.x;
    es[sb + p1] = (d1 << 16) | (uint32_t)r.y;
    es[sb + p2] = (d2 << 16) | (uint32_t)r.z;
    es[sb + p3] = (d3 << 16) | (uint32_t)r.w;
}

// ---------------- fp16 tensor-core GEMM (mma.m16n8k16 + ldmatrix) ----------------
#define KS 136
#define GH_SMEM (2 * 128 * KS * 2)

template<bool GATHER>
__global__ __launch_bounds__(512, 2) void gemm_h16(
    const float* __restrict__ A, const float* __restrict__ W,
    __half* __restrict__ C, int rows,
    const float* __restrict__ hsrc, int h_rows,
    const int* __restrict__ idx, const float* __restrict__ val,
    const float* __restrict__ enc)
{
    extern __shared__ __half smh[];
    __half* Ws = smh;
    __half* As = smh + 128 * KS;
    int tid = threadIdx.x;
    int lane = tid & 31;
    int w = tid >> 5;
    int wm = w & 3, wn = w >> 2;
    int gid = lane >> 2, tig = lane & 3;
    int tile = blockIdx.x;

#pragma unroll
    for (int j = 0; j < 8; j++) {
        int fi = tid + j * 512;
        int k = fi >> 5;
        int c4 = fi & 31;
        float4 v = *(const float4*)(W + (size_t)k * D + c4 * 4);
        __half2 p0 = __floats2half2_rn(v.x, v.y);
        __half2 p1 = __floats2half2_rn(v.z, v.w);
        uint2 pk;
        pk.x = *(uint32_t*)&p0;
        pk.y = *(uint32_t*)&p1;
        *(uint2*)(Ws + k * KS + c4 * 4) = pk;
    }
#pragma unroll
    for (int j = 0; j < 8; j++) {
        int fi = tid + j * 512;
        int m = fi >> 5;
        int c4 = fi & 31;
        int gr = tile * 128 + m;
        float4 v = make_float4(0.f, 0.f, 0.f, 0.f);
        if (gr < rows) {
            if (GATHER) {
                int ci = min(idx[gr], h_rows - 1);
                float vv = val[gr];
                float4 u = *(const float4*)(hsrc + (size_t)ci * D + c4 * 4);
                float4 e = *(const float4*)(enc + (size_t)gr * D + c4 * 4);
                v = make_float4(vv * u.x + e.x, vv * u.y + e.y,
                                vv * u.z + e.z, vv * u.w + e.w);
            } else {
                v = *(const float4*)(A + (size_t)gr * D + c4 * 4);
            }
        }
        __half2 p0 = __floats2half2_rn(v.x, v.y);
        __half2 p1 = __floats2half2_rn(v.z, v.w);
        uint2 pk;
        pk.x = *(uint32_t*)&p0;
        pk.y = *(uint32_t*)&p1;
        *(uint2*)(As + m * KS + c4 * 4) = pk;
    }
    __syncthreads();

    uint32_t uWs = smem_u32(Ws);
    uint32_t uAs = smem_u32(As);
    uint32_t aAddr[2];
#pragma unroll
    for (int mt = 0; mt < 2; mt++)
        aAddr[mt] = uAs + (((wm * 32 + mt * 16 + (lane & 15)) * KS
                           + ((lane >> 4) << 3)) << 1);
    uint32_t bAddr[2];
#pragma unroll
    for (int np = 0; np < 2; np++)
        bAddr[np] = uWs + ((((lane & 15)) * KS
                           + wn * 32 + np * 16 + ((lane >> 4) << 3)) << 1);

    float acc[2][4][4];
#pragma unroll
    for (int mt = 0; mt < 2; mt++)
#pragma unroll
        for (int nt = 0; nt < 4; nt++)
#pragma unroll
            for (int q = 0; q < 4; q++) acc[mt][nt][q] = 0.f;

#pragma unroll
    for (int ks = 0; ks < 8; ks++) {
        unsigned a[2][4], b[2][4];
        ldm_x4(a[0], aAddr[0] + ks * 32);
        ldm_x4(a[1], aAddr[1] + ks * 32);
        ldm_x4t(b[0], bAddr[0] + ks * 32 * KS);
        ldm_x4t(b[1], bAddr[1] + ks * 32 * KS);
#pragma unroll
        for (int np = 0; np < 2; np++) {
            mma_f16(acc[0][2 * np],     a[0], b[np][0], b[np][1]);
            mma_f16(acc[1][2 * np],     a[1], b[np][0], b[np][1]);
            mma_f16(acc[0][2 * np + 1], a[0], b[np][2], b[np][3]);
            mma_f16(acc[1][2 * np + 1], a[1], b[np][2], b[np][3]);
        }
    }

#pragma unroll
    for (int mt = 0; mt < 2; mt++) {
        int r1 = tile * 128 + wm * 32 + mt * 16 + gid;
        int r2 = r1 + 8;
#pragma unroll
        for (int nt = 0; nt < 4; nt++) {
            int col = wn * 32 + nt * 8 + 2 * tig;
            if (r1 < rows)
                *(__half2*)(C + (size_t)r1 * D + col) =
                    __floats2half2_rn(acc[mt][nt][0], acc[mt][nt][1]);
            if (r2 < rows)
                *(__half2*)(C + (size_t)r2 * D + col) =
                    __floats2half2_rn(acc[mt][nt][2], acc[mt][nt][3]);
        }
    }
}

// ---------------- aggregation (warp/dst, unroll8, fp16 gathers, packed 4B edges) ---
template<int MODE>   // 0 = plain, 1 = fused pool scatter, 2 = fused normalize
__global__ void agg_k(const __half* __restrict__ t, int h_rows,
                      const int* __restrict__ rp, const uint32_t* __restrict__ es,
                      const float* __restrict__ dis, int n,
                      const float* __restrict__ bias, float* __restrict__ out,
                      const int* __restrict__ pidx, const float* __restrict__ pval,
                      float* __restrict__ pout) {
    int warp = (blockIdx.x * blockDim.x + threadIdx.x) >> 5;
    int lane = threadIdx.x & 31;
    if (warp >= n) return;
    int dst = warp;
    float dd = dis[dst];
    int hc = h_rows - 1;
    float4 v = ld_h4(t, (size_t)min(dst, hc), lane);
    float w0 = dd * dd;
    float4 a1 = make_float4(w0 * v.x, w0 * v.y, w0 * v.z, w0 * v.w);
    float4 a2 = make_float4(0.f, 0.f, 0.f, 0.f);
    float4 a3 = make_float4(0.f, 0.f, 0.f, 0.f);
    float4 a4 = make_float4(0.f, 0.f, 0.f, 0.f);
    int e = rp[dst], end = rp[dst + 1];
    // main loop: 8 edges, all gathers in flight before the FMA block
    for (; e + 8 <= end; e += 8) {
        uint32_t f0 = es[e],     f1 = es[e + 1], f2 = es[e + 2], f3 = es[e + 3];
        uint32_t f4 = es[e + 4], f5 = es[e + 5], f6 = es[e + 6], f7 = es[e + 7];
        int s0, s1, s2, s3, s4, s5, s6, s7;
        float d0, d1, d2, d3, d4, d5, d6, d7;
        unpack_e(f0, s0, d0); unpack_e(f1, s1, d1);
        unpack_e(f2, s2, d2); unpack_e(f3, s3, d3);
        unpack_e(f4, s4, d4); unpack_e(f5, s5, d5);
        unpack_e(f6, s6, d6); unpack_e(f7, s7, d7);
        float4 u0 = ld_h4(t, (size_t)min(s0, hc), lane);
        float4 u1 = ld_h4(t, (size_t)min(s1, hc), lane);
        float4 u2 = ld_h4(t, (size_t)min(s2, hc), lane);
        float4 u3 = ld_h4(t, (size_t)min(s3, hc), lane);
        float4 u4 = ld_h4(t, (size_t)min(s4, hc), lane);
        float4 u5 = ld_h4(t, (size_t)min(s5, hc), lane);
        float4 u6 = ld_h4(t, (size_t)min(s6, hc), lane);
        float4 u7 = ld_h4(t, (size_t)min(s7, hc), lane);
        float q0 = d0 * dd, q1 = d1 * dd, q2 = d2 * dd, q3 = d3 * dd;
        float q4 = d4 * dd, q5 = d5 * dd, q6 = d6 * dd, q7 = d7 * dd;
        a1.x += q0 * u0.x; a1.y += q0 * u0.y; a1.z += q0 * u0.z; a1.w += q0 * u0.w;
        a2.x += q1 * u1.x; a2.y += q1 * u1.y; a2.z += q1 * u1.z; a2.w += q1 * u1.w;
        a3.x += q2 * u2.x; a3.y += q2 * u2.y; a3.z += q2 * u2.z; a3.w += q2 * u2.w;
        a4.x += q3 * u3.x; a4.y += q3 * u3.y; a4.z += q3 * u3.z; a4.w += q3 * u3.w;
        a1.x += q4 * u4.x; a1.y += q4 * u4.y; a1.z += q4 * u4.z; a1.w += q4 * u4.w;
        a2.x += q5 * u5.x; a2.y += q5 * u5.y; a2.z += q5 * u5.z; a2.w += q5 * u5.w;
        a3.x += q6 * u6.x; a3.y += q6 * u6.y; a3.z += q6 * u6.z; a3.w += q6 * u6.w;
        a4.x += q7 * u7.x; a4.y += q7 * u7.y; a4.z += q7 * u7.z; a4.w += q7 * u7.w;
    }
    for (; e + 4 <= end; e += 4) {
        uint32_t f0 = es[e], f1 = es[e + 1], f2 = es[e + 2], f3 = es[e + 3];
        int s0, s1, s2, s3;
        float d0, d1, d2, d3;
        unpack_e(f0, s0, d0); unpack_e(f1, s1, d1);
        unpack_e(f2, s2, d2); unpack_e(f3, s3, d3);
        float q0 = d0 * dd, q1 = d1 * dd, q2 = d2 * dd, q3 = d3 * dd;
        float4 u0 = ld_h4(t, (size_t)min(s0, hc), lane);
        float4 u1 = ld_h4(t, (size_t)min(s1, hc), lane);
        float4 u2 = ld_h4(t, (size_t)min(s2, hc), lane);
        float4 u3 = ld_h4(t, (size_t)min(s3, hc), lane);
        a1.x += q0 * u0.x; a1.y += q0 * u0.y; a1.z += q0 * u0.z; a1.w += q0 * u0.w;
        a2.x += q1 * u1.x; a2.y += q1 * u1.y; a2.z += q1 * u1.z; a2.w += q1 * u1.w;
        a3.x += q2 * u2.x; a3.y += q2 * u2.y; a3.z += q2 * u2.z; a3.w += q2 * u2.w;
        a4.x += q3 * u3.x; a4.y += q3 * u3.y; a4.z += q3 * u3.z; a4.w += q3 * u3.w;
    }
    for (; e < end; e++) {
        int s0; float d0;
        unpack_e(es[e], s0, d0);
        float q0 = d0 * dd;
        float4 u0 = ld_h4(t, (size_t)min(s0, hc), lane);
        a1.x += q0 * u0.x; a1.y += q0 * u0.y; a1.z += q0 * u0.z; a1.w += q0 * u0.w;
    }
    float4 b = ((const float4*)bias)[lane];
    float4 r;
    r.x = fmaxf(a1.x + a2.x + a3.x + a4.x + b.x, 0.f);
    r.y = fmaxf(a1.y + a2.y + a3.y + a4.y + b.y, 0.f);
    r.z = fmaxf(a1.z + a2.z + a3.z + a4.z + b.z, 0.f);
    r.w = fmaxf(a1.w + a2.w + a3.w + a4.w + b.w, 0.f);
    if (MODE == 2) {
        float s = r.x * r.x + r.y * r.y + r.z * r.z + r.w * r.w;
#pragma unroll
        for (int o = 16; o; o >>= 1) s += __shfl_xor_sync(0xffffffffu, s, o);
        float inv = 1.0f / fmaxf(sqrtf(s), 1e-12f);
        r.x *= inv; r.y *= inv; r.z *= inv; r.w *= inv;
    }
    ((float4*)(out + (size_t)dst * D))[lane] = r;
    if (MODE == 1) {
        int c = pidx[dst];
        float pv = pval[dst];
        float* o = pout + (size_t)c * D + lane * 4;
        atomicAdd(o + 0, pv * r.x);
        atomicAdd(o + 1, pv * r.y);
        atomicAdd(o + 2, pv * r.z);
        atomicAdd(o + 3, pv * r.w);
    }
}

// ---------------- host orchestration ----------------
static inline int cdiv(int a, int b) { return (a + b - 1) / b; }

extern "C" void kernel_launch(void* const* d_in, const int* in_sizes, int n_in,
                              void* d_out, int out_size) {
    const float* x   = (const float*)d_in[0];
    const int* e0    = (const int*)d_in[1];
    const int* e1    = (const int*)d_in[2];
    const int* e2    = (const int*)d_in[3];
    const int* C0i   = (const int*)d_in[4];
    const float* C0v = (const float*)d_in[5];
    const int* C1i   = (const int*)d_in[6];
    const float* C1v = (const float*)d_in[7];
    const float* W_enc0 = (const float*)d_in[8];
    const float* b_enc0 = (const float*)d_in[9];
    const float* W_enc1 = (const float*)d_in[10];
    const float* b_enc1 = (const float*)d_in[11];
    const float* W_enc2 = (const float*)d_in[12];
    const float* b_enc2 = (const float*)d_in[13];
    const float* W_bot  = (const float*)d_in[14];
    const float* b_bot  = (const float*)d_in[15];
    const float* W_dec0 = (const float*)d_in[16];
    const float* b_dec0 = (const float*)d_in[17];
    const float* W_dec1 = (const float*)d_in[18];
    const float* b_dec1 = (const float*)d_in[19];
    const float* W_dec2 = (const float*)d_in[20];
    const float* b_dec2 = (const float*)d_in[21];

    __half* t;
    float *enc0, *enc1, *h, *h2, *dis;
    int *deg, *rp, *cur, *seq;
    uint32_t* es;
    cudaGetSymbolAddress((void**)&t, g_t);
    cudaGetSymbolAddress((void**)&enc0, g_enc0);
    cudaGetSymbolAddress((void**)&enc1, g_enc1);
    cudaGetSymbolAddress((void**)&h, g_h);
    cudaGetSymbolAddress((void**)&h2, g_h2);
    cudaGetSymbolAddress((void**)&deg, g_deg);
    cudaGetSymbolAddress((void**)&rp, g_rp);
    cudaGetSymbolAddress((void**)&cur, g_cur);
    cudaGetSymbolAddress((void**)&seq, g_seq);
    cudaGetSymbolAddress((void**)&es, g_es);
    cudaGetSymbolAddress((void**)&dis, g_dis);

    cudaFuncSetAttribute((const void*)gemm_h16<false>, cudaFuncAttributeMaxDynamicSharedMemorySize, GH_SMEM);
    cudaFuncSetAttribute((const void*)gemm_h16<true>,  cudaFuncAttributeMaxDynamicSharedMemorySize, GH_SMEM);

    const int* rp0 = rp + RP0; const uint32_t* es0 = es;           const float* dis0 = dis;
    const int* rp1 = rp + RP1; const uint32_t* es1 = es + E0;      const float* dis1 = dis + N0;
    const int* rp2 = rp + RP2; const uint32_t* es2 = es + E0 + E1; const float* dis2 = dis + N0 + N1;

    const int AT = 256;

    auto gemm = [&](const float* A, const float* W, int rows) {
        gemm_h16<false><<<cdiv(rows, 128), 512, GH_SMEM>>>(A, W, t, rows, nullptr, 0, nullptr, nullptr, nullptr);
    };
    auto gemm_g = [&](const float* W, int rows, const float* hsrc, int h_rows,
                      const int* idx, const float* val, const float* enc) {
        gemm_h16<true><<<cdiv(rows, 128), 512, GH_SMEM>>>(nullptr, W, t, rows, hsrc, h_rows, idx, val, enc);
    };

    // ---- CSR build (two-pass, atomic-free scatter, packed 4B edges) + zero h/h2 ----
    zero_init_k<<<cdiv(NT, 1024), 1024>>>(deg, (float4*)h, (float4*)h2);
    hist_seq_k<<<cdiv(ET / 4, 256), 256>>>(e0, e1, e2, deg, seq);
    scan_fused_k<<<NB, 1024>>>(deg, rp, cur, dis);
    scatter_pos_k<<<cdiv(ET / 4, 256), 256>>>(e0, e1, e2, cur, dis, seq, es);

    // ---- encoder level 0: agg fuses pool0 -> h (N1 rows) ----
    gemm(x, W_enc0, N0);
    agg_k<1><<<cdiv(N0, 8), AT>>>(t, N0, rp0, es0, dis0, N0, b_enc0, enc0, C0i, C0v, h);
    // ---- encoder level 1: agg fuses pool1 -> h2 (N2 rows, pre-zeroed) ----
    gemm(h, W_enc1, N1);
    agg_k<1><<<cdiv(N1, 8), AT>>>(t, N1, rp1, es1, dis1, N1, b_enc1, enc1, C1i, C1v, h2);
    // ---- encoder level 2: h2 -> h ----
    gemm(h2, W_enc2, N2);
    agg_k<0><<<cdiv(N2, 8), AT>>>(t, N2, rp2, es2, dis2, N2, b_enc2, h, nullptr, nullptr, nullptr);
    // ---- bottleneck: h -> h2 ----
    gemm(h, W_bot, N2);
    agg_k<0><<<cdiv(N2, 8), AT>>>(t, N2, rp2, es2, dis2, N2, b_bot, h2, nullptr, nullptr, nullptr);
    // ---- decoder l=2: unpool C1 from h2 (N2 rows), conv g2 -> h ----
    gemm_g(W_dec2, N1, h2, N2, C1i, C1v, enc1);
    agg_k<0><<<cdiv(N2, 8), AT>>>(t, N1, rp2, es2, dis2, N2, b_dec2, h, nullptr, nullptr, nullptr);
    // ---- decoder l=1: unpool C0 from h (N2 rows, clamped), conv g1 -> h2 ----
    gemm_g(W_dec1, N0, h, N2, C0i, C0v, enc0);
    agg_k<0><<<cdiv(N1, 8), AT>>>(t, N0, rp1, es1, dis1, N1, b_dec1, h2, nullptr, nullptr, nullptr);
    // ---- decoder l=0 + fused normalize: h2 (N1 rows) -> out ----
    gemm(h2, W_dec0, N1);
    agg_k<2><<<cdiv(N0, 8), AT>>>(t, N1, rp0, es0, dis0, N0, b_dec0, (float*)d_out, nullptr, nullptr, nullptr);
}